// round 7
// baseline (speedup 1.0000x reference)
#include <cuda_runtime.h>
#include <cstdint>
#include <cstddef>

// Problem constants
#define cT 64
#define cN 8192
#define cF 256
#define cH 256
#define cK 512          // concat K = F + H
#define ROWSC 56        // batch rows per CTA (8 warps x 7 rows)
#define RPW 7           // rows per warp
#define NTHR 256
#define GRID ((cN + ROWSC - 1) / ROWSC)   // 147 CTAs ~= 148 SMs, one wave
#define KTILE 32
#define NKP 16          // k-pairs per chunk (KTILE/2)
#define NCHUNK 16       // cK / KTILE
#define SMEM_BYTES ((ROWSC * cK + 2 * KTILE * cH) * 4)

// Prepped weights, k-pair interleaved:
//   Wt2[(k>>1)*512 + j*2 + (k&1)] = (k<256 ? W_ih[j][k] : W_hh[j][k-256])
// so each 8-byte word holds (w[2kp][j], w[2kp+1][j]) — natural LDS.64 for FFMA2.
__device__ float g_Wt2[cK * cH];
__device__ float g_b[cH];

__global__ void prep_kernel(const float* __restrict__ W_ih, const float* __restrict__ W_hh,
                            const float* __restrict__ b_ih, const float* __restrict__ b_hh) {
    int idx = blockIdx.x * blockDim.x + threadIdx.x;
    if (idx < cK * cH) {
        int k = idx >> 8;
        int j = idx & 255;
        float w = (k < cH) ? W_ih[j * cF + k] : W_hh[j * cH + (k - cH)];
        g_Wt2[(k >> 1) * 512 + j * 2 + (k & 1)] = w;
    }
    if (idx < cH) g_b[idx] = b_ih[idx] + b_hh[idx];
}

// ---- packed f32x2 helpers (sm_103a) ----
__device__ __forceinline__ void upk2(unsigned long long v, float& lo, float& hi) {
    asm("mov.b64 {%0, %1}, %2;" : "=f"(lo), "=f"(hi) : "l"(v));
}
__device__ __forceinline__ unsigned long long ffma2(unsigned long long a,
                                                    unsigned long long b,
                                                    unsigned long long c) {
    unsigned long long d;
    asm("fma.rn.f32x2 %0, %1, %2, %3;" : "=l"(d) : "l"(a), "l"(b), "l"(c));
    return d;
}

__device__ __forceinline__ void cp16(uint32_t saddr, const void* g) {
    asm volatile("cp.async.cg.shared.global [%0], [%1], 16;" :: "r"(saddr), "l"(g));
}

__global__ __launch_bounds__(NTHR, 1)
void rnn_kernel(const float* __restrict__ X, const float* __restrict__ ln_w,
                const float* __restrict__ ln_b, float* __restrict__ out) {
    extern __shared__ float smem[];
    float* A  = smem;                 // [ROWSC][cK] : cols 0..255 = x_t, 256..511 = h
    float* Ws = smem + ROWSC * cK;    // [2][NKP][256][2] floats per buffer

    const int tid  = threadIdx.x;
    const int lane = tid & 31;
    const int warp = tid >> 5;        // 8 warps, RPW rows each
    const int n0   = blockIdx.x * ROWSC;

    const uint32_t ws_smem = (uint32_t)__cvta_generic_to_shared(Ws);
    const uint32_t a_smem  = (uint32_t)__cvta_generic_to_shared(A);

    // Zero the h region of A (cols 256..511): ROWSC*cH/4 = 3584 float4, 14/thread
    {
        float4 z = make_float4(0.f, 0.f, 0.f, 0.f);
#pragma unroll
        for (int q = 0; q < 14; ++q) {
            int flat = (tid + NTHR * q) * 4;        // 0..14335 floats
            int r = flat >> 8;
            int c = flat & 255;
            *reinterpret_cast<float4*>(&A[r * cK + cH + c]) = z;
        }
    }

    // W-chunk cp.async issue: one chunk = KTILE*256 floats (32 KB), 8x16B per thread
    auto issue_w = [&](int ch, int buf) {
        const float4* src = reinterpret_cast<const float4*>(g_Wt2) + ch * (KTILE * cH / 4) + tid;
        uint32_t dst = ws_smem + buf * (KTILE * cH * 4) + tid * 16;
#pragma unroll
        for (int q = 0; q < 8; ++q) cp16(dst + q * 4096, src + q * 256);
        asm volatile("cp.async.commit_group;" ::: "memory");
    };

    for (int it = 0; it <= cT; ++it) {
        // Load x_t tile into A cols 0..255 via cp.async (it==0 pre-step and it==1
        // both use t=0). Commits in the same group as W-chunk 0; the first
        // wait_group(0)+__syncthreads below orders them before any GEMM read.
        // Tail CTA: clamp global row (duplicate data; those rows are never stored).
        const int t = (it == 0) ? 0 : (it - 1);
        const float* xbase = X + (size_t)t * cN * cF;
#pragma unroll
        for (int q = 0; q < 14; ++q) {
            int f4 = tid + NTHR * q;                // float4 index, 0..3583
            int flat = f4 * 4;
            int r = flat >> 8;
            int c = flat & 255;
            int gr = n0 + r; if (gr > cN - 1) gr = cN - 1;
            cp16(a_smem + (uint32_t)(r * cK + c) * 4,
                 xbase + (size_t)gr * cF + c);
        }

        // Accumulators: one f32x2 per (row, col), col j = lane + 32*p.
        // Halves hold even-k / odd-k partial sums; folded (+bias) at epilogue.
        unsigned long long acc[RPW][8];
#pragma unroll
        for (int rr = 0; rr < RPW; ++rr)
#pragma unroll
            for (int p = 0; p < 8; ++p) acc[rr][p] = 0ull;

        issue_w(0, 0);   // commits x-tile + W chunk 0 together

        for (int ch = 0; ch < NCHUNK; ++ch) {
            asm volatile("cp.async.wait_group 0;" ::: "memory");
            __syncthreads();     // W tile (and x tile on ch==0) ready; h STS visible
            if (ch + 1 < NCHUNK) issue_w(ch + 1, (ch + 1) & 1);

            const char* wb = reinterpret_cast<const char*>(Ws) + (ch & 1) * (KTILE * cH * 4);
            const int k0 = ch * KTILE;
#pragma unroll
            for (int kp = 0; kp < NKP; ++kp) {
                // w-pairs for this thread's 8 columns: 8B/lane stride, conflict-free
                unsigned long long w2[8];
#pragma unroll
                for (int p = 0; p < 8; ++p) {
                    w2[p] = *reinterpret_cast<const unsigned long long*>(
                        wb + kp * 2048 + lane * 8 + p * 256);
                }
#pragma unroll
                for (int rr = 0; rr < RPW; ++rr) {
                    // (a[k], a[k+1]) — same addr all lanes: broadcast, no splat
                    unsigned long long a2 = *reinterpret_cast<const unsigned long long*>(
                        &A[(warp * RPW + rr) * cK + k0 + 2 * kp]);
#pragma unroll
                    for (int p = 0; p < 8; ++p) acc[rr][p] = ffma2(a2, w2[p], acc[rr][p]);
                }
            }
        }
        __syncthreads();  // all warps done reading A before h writeback / next x load

        // Epilogue: fold halves + bias, relu (it>0), h writeback, LayerNorm + store.
        // Bias / LN params hoisted to registers once per step (L1 hits, out of rr loop).
        float bias[8], lw[8], lb[8];
#pragma unroll
        for (int p = 0; p < 8; ++p) {
            int j = lane + 32 * p;
            bias[p] = __ldg(&g_b[j]);
            lw[p]   = __ldg(&ln_w[j]);
            lb[p]   = __ldg(&ln_b[j]);
        }

#pragma unroll
        for (int rr = 0; rr < RPW; ++rr) {
            const int row = warp * RPW + rr;
            float v[8];
#pragma unroll
            for (int p = 0; p < 8; ++p) {
                float lo, hi;
                upk2(acc[rr][p], lo, hi);
                v[p] = lo + hi + bias[p];
            }
            if (it > 0) {
#pragma unroll
                for (int p = 0; p < 8; ++p) v[p] = fmaxf(v[p], 0.f);
            }
            // h writeback into A cols 256..511 (warp-private rows), col = lane+32p
#pragma unroll
            for (int p = 0; p < 8; ++p)
                A[row * cK + cH + lane + 32 * p] = v[p];

            if (it > 0 && n0 + row < cN) {
                float s = 0.f, s2 = 0.f;
#pragma unroll
                for (int p = 0; p < 8; ++p) { s += v[p]; s2 += v[p] * v[p]; }
#pragma unroll
                for (int off = 16; off >= 1; off >>= 1) {
                    s  += __shfl_xor_sync(0xffffffffu, s,  off);
                    s2 += __shfl_xor_sync(0xffffffffu, s2, off);
                }
                const float mean = s * (1.f / 256.f);
                const float var  = s2 * (1.f / 256.f) - mean * mean;
                const float rstd = rsqrtf(var + 1e-5f);
                float* orow = out + (((size_t)(it - 1) * cN) + n0 + row) * cH;
#pragma unroll
                for (int p = 0; p < 8; ++p) {
                    float g = rstd * lw[p];
                    orow[lane + 32 * p] = (v[p] - mean) * g + lb[p];
                }
            }
        }
        // No sync needed here: next iteration's first wait_group+__syncthreads orders
        // the h/x SMEM stores before any GEMM read.
    }
}

extern "C" void kernel_launch(void* const* d_in, const int* in_sizes, int n_in,
                              void* d_out, int out_size) {
    const float* X    = (const float*)d_in[0];
    const float* W_ih = (const float*)d_in[1];
    const float* W_hh = (const float*)d_in[2];
    const float* b_ih = (const float*)d_in[3];
    const float* b_hh = (const float*)d_in[4];
    const float* ln_w = (const float*)d_in[5];
    const float* ln_b = (const float*)d_in[6];
    float* out = (float*)d_out;

    prep_kernel<<<(cK * cH + 255) / 256, 256>>>(W_ih, W_hh, b_ih, b_hh);

    cudaFuncSetAttribute(rnn_kernel, cudaFuncAttributeMaxDynamicSharedMemorySize, SMEM_BYTES);
    rnn_kernel<<<GRID, NTHR, SMEM_BYTES>>>(X, ln_w, ln_b, out);
}

// round 9
// speedup vs baseline: 1.5106x; 1.5106x over previous
#include <cuda_runtime.h>
#include <cstdint>
#include <cstddef>

// Problem constants
#define cT 64
#define cN 8192
#define cF 256
#define cH 256
#define cK 512          // concat K = F + H
#define ROWSC 56        // batch rows per CTA (8 row-groups x 7 rows)
#define RPW 7           // rows per row-group
#define NTHR 512        // 16 warps = 8 row-groups x 2 column halves
#define GRID ((cN + ROWSC - 1) / ROWSC)   // 147 CTAs ~= 148 SMs, one wave
#define KTILE 32
#define NKP 16          // k-pairs per chunk (KTILE/2)
#define NCHUNK 16       // cK / KTILE
// A tile + 2 W buffers + LN partial scratch (56 rows x 2 halves x {s,s2})
#define SMEM_BYTES ((ROWSC * cK + 2 * KTILE * cH + ROWSC * 4) * 4)

// Prepped weights, k-pair interleaved:
//   Wt2[(k>>1)*512 + j*2 + (k&1)] = (k<256 ? W_ih[j][k] : W_hh[j][k-256])
// so each 8-byte word holds (w[2kp][j], w[2kp+1][j]) — natural LDS.64 for FFMA2.
__device__ float g_Wt2[cK * cH];
__device__ float g_b[cH];

__global__ void prep_kernel(const float* __restrict__ W_ih, const float* __restrict__ W_hh,
                            const float* __restrict__ b_ih, const float* __restrict__ b_hh) {
    int idx = blockIdx.x * blockDim.x + threadIdx.x;
    if (idx < cK * cH) {
        int k = idx >> 8;
        int j = idx & 255;
        float w = (k < cH) ? W_ih[j * cF + k] : W_hh[j * cH + (k - cH)];
        g_Wt2[(k >> 1) * 512 + j * 2 + (k & 1)] = w;
    }
    if (idx < cH) g_b[idx] = b_ih[idx] + b_hh[idx];
}

// ---- packed f32x2 helpers (sm_103a) ----
__device__ __forceinline__ void upk2(unsigned long long v, float& lo, float& hi) {
    asm("mov.b64 {%0, %1}, %2;" : "=f"(lo), "=f"(hi) : "l"(v));
}
__device__ __forceinline__ unsigned long long ffma2(unsigned long long a,
                                                    unsigned long long b,
                                                    unsigned long long c) {
    unsigned long long d;
    asm("fma.rn.f32x2 %0, %1, %2, %3;" : "=l"(d) : "l"(a), "l"(b), "l"(c));
    return d;
}

__device__ __forceinline__ void cp16(uint32_t saddr, const void* g) {
    asm volatile("cp.async.cg.shared.global [%0], [%1], 16;" :: "r"(saddr), "l"(g));
}

__global__ __launch_bounds__(NTHR, 1)
void rnn_kernel(const float* __restrict__ X, const float* __restrict__ ln_w,
                const float* __restrict__ ln_b, float* __restrict__ out) {
    extern __shared__ float smem[];
    float* A  = smem;                 // [ROWSC][cK] : cols 0..255 = x_t, 256..511 = h
    float* Ws = smem + ROWSC * cK;    // [2][NKP][256][2] floats per buffer
    float* sc = Ws + 2 * KTILE * cH;  // [ROWSC][2 halves][2] LN partials

    const int tid  = threadIdx.x;
    const int lane = tid & 31;
    const int wid  = tid >> 5;
    const int rg   = wid >> 1;        // row-group 0..7, rows rg*7 .. rg*7+6
    const int ch2  = wid & 1;         // column half: cols ch2*128 .. +127
    const int n0   = blockIdx.x * ROWSC;

    const uint32_t ws_smem = (uint32_t)__cvta_generic_to_shared(Ws);
    const uint32_t a_smem  = (uint32_t)__cvta_generic_to_shared(A);

    // Zero the h region of A (cols 256..511): ROWSC*cH/4 = 3584 float4, 7/thread
    {
        float4 z = make_float4(0.f, 0.f, 0.f, 0.f);
#pragma unroll
        for (int q = 0; q < 7; ++q) {
            int flat = (tid + NTHR * q) * 4;        // 0..14335 floats
            int r = flat >> 8;
            int c = flat & 255;
            *reinterpret_cast<float4*>(&A[r * cK + cH + c]) = z;
        }
    }

    // W-chunk cp.async issue: one chunk = KTILE*256 floats (32 KB), 4x16B per thread
    auto issue_w = [&](int ch, int buf) {
        const float4* src = reinterpret_cast<const float4*>(g_Wt2) + ch * (KTILE * cH / 4) + tid;
        uint32_t dst = ws_smem + buf * (KTILE * cH * 4) + tid * 16;
#pragma unroll
        for (int q = 0; q < 4; ++q) cp16(dst + q * 8192, src + q * 512);
        asm volatile("cp.async.commit_group;" ::: "memory");
    };

    // This thread's 4 output columns: j = ch2*128 + lane + 32*p
    float bias[4], lw4[4], lb4[4];
#pragma unroll
    for (int p = 0; p < 4; ++p) {
        int j = ch2 * 128 + lane + 32 * p;
        bias[p] = __ldg(&g_b[j]);
        lw4[p]  = __ldg(&ln_w[j]);
        lb4[p]  = __ldg(&ln_b[j]);
    }

    for (int it = 0; it <= cT; ++it) {
        // Load x_t tile into A cols 0..255 via cp.async (it==0 pre-step and it==1
        // both use t=0). Commits in the same group as W-chunk 0; the first
        // wait_group(0)+__syncthreads below orders them before any GEMM read.
        // Tail CTA: clamp global row (duplicate data; those rows are never stored).
        const int t = (it == 0) ? 0 : (it - 1);
        const float* xbase = X + (size_t)t * cN * cF;
#pragma unroll
        for (int q = 0; q < 7; ++q) {
            int f4 = tid + NTHR * q;                // float4 index, 0..3583
            int flat = f4 * 4;
            int r = flat >> 8;
            int c = flat & 255;
            int gr = n0 + r; if (gr > cN - 1) gr = cN - 1;
            cp16(a_smem + (uint32_t)(r * cK + c) * 4,
                 xbase + (size_t)gr * cF + c);
        }

        // Accumulators: one f32x2 per (row, col): halves = even-k / odd-k partials.
        unsigned long long acc[RPW][4];
#pragma unroll
        for (int rr = 0; rr < RPW; ++rr)
#pragma unroll
            for (int p = 0; p < 4; ++p) acc[rr][p] = 0ull;

        issue_w(0, 0);   // commits x-tile + W chunk 0 together

        for (int ch = 0; ch < NCHUNK; ++ch) {
            asm volatile("cp.async.wait_group 0;" ::: "memory");
            __syncthreads();     // W tile (and x tile on ch==0) ready; h STS visible
            if (ch + 1 < NCHUNK) issue_w(ch + 1, (ch + 1) & 1);

            const char* wb = reinterpret_cast<const char*>(Ws)
                             + (ch & 1) * (KTILE * cH * 4) + ch2 * 1024;
            const int k0 = ch * KTILE;
#pragma unroll
            for (int kp = 0; kp < NKP; ++kp) {
                // w-pairs for this thread's 4 columns: 8B/lane stride, conflict-free
                unsigned long long w2[4];
#pragma unroll
                for (int p = 0; p < 4; ++p) {
                    w2[p] = *reinterpret_cast<const unsigned long long*>(
                        wb + kp * 2048 + lane * 8 + p * 256);
                }
#pragma unroll
                for (int rr = 0; rr < RPW; ++rr) {
                    // (a[k], a[k+1]) — same addr all lanes: broadcast
                    unsigned long long a2 = *reinterpret_cast<const unsigned long long*>(
                        &A[(rg * RPW + rr) * cK + k0 + 2 * kp]);
#pragma unroll
                    for (int p = 0; p < 4; ++p) acc[rr][p] = ffma2(a2, w2[p], acc[rr][p]);
                }
            }
        }
        __syncthreads();  // all warps done reading A before h writeback / next x load

        // Epilogue phase 1: fold halves + bias, relu (it>0), h writeback,
        // per-row 128-col partial sums -> scratch.
        float ps[RPW], ps2[RPW];
#pragma unroll
        for (int rr = 0; rr < RPW; ++rr) {
            const int row = rg * RPW + rr;
            float v[4];
#pragma unroll
            for (int p = 0; p < 4; ++p) {
                float lo, hi;
                upk2(acc[rr][p], lo, hi);
                v[p] = lo + hi + bias[p];
            }
            if (it > 0) {
#pragma unroll
                for (int p = 0; p < 4; ++p) v[p] = fmaxf(v[p], 0.f);
            }
            // h writeback: cols 256 + ch2*128 + lane + 32p (disjoint across the pair)
#pragma unroll
            for (int p = 0; p < 4; ++p)
                A[row * cK + cH + ch2 * 128 + lane + 32 * p] = v[p];

            if (it > 0) {
                float s = 0.f, s2 = 0.f;
#pragma unroll
                for (int p = 0; p < 4; ++p) { s += v[p]; s2 += v[p] * v[p]; }
#pragma unroll
                for (int off = 16; off >= 1; off >>= 1) {
                    s  += __shfl_xor_sync(0xffffffffu, s,  off);
                    s2 += __shfl_xor_sync(0xffffffffu, s2, off);
                }
                ps[rr] = s; ps2[rr] = s2;
                if (lane == 0) {
                    sc[(row * 2 + ch2) * 2 + 0] = s;
                    sc[(row * 2 + ch2) * 2 + 1] = s2;
                }
            }
        }

        if (it > 0) {
            __syncthreads();   // partials visible across the warp pair

            // Epilogue phase 2: combine halves, LayerNorm + guarded store.
#pragma unroll
            for (int rr = 0; rr < RPW; ++rr) {
                const int row = rg * RPW + rr;
                if (n0 + row >= cN) continue;
                const float so  = sc[(row * 2 + (1 - ch2)) * 2 + 0];
                const float so2 = sc[(row * 2 + (1 - ch2)) * 2 + 1];
                const float mean = (ps[rr] + so) * (1.f / 256.f);
                const float var  = (ps2[rr] + so2) * (1.f / 256.f) - mean * mean;
                const float rstd = rsqrtf(var + 1e-5f);
                float* orow = out + (((size_t)(it - 1) * cN) + n0 + row) * cH;
#pragma unroll
                for (int p = 0; p < 4; ++p) {
                    int j = ch2 * 128 + lane + 32 * p;
                    float v = A[row * cK + cH + j];     // reload h (post-relu)
                    orow[j] = (v - mean) * (rstd * lw4[p]) + lb4[p];
                }
            }
        }
        // Next iteration's first wait_group+__syncthreads orders the h/x SMEM
        // stores before any GEMM read. The sc scratch is re-written only after
        // the next step's chunk-loop barriers, so no WAR race on sc either.
    }
}

extern "C" void kernel_launch(void* const* d_in, const int* in_sizes, int n_in,
                              void* d_out, int out_size) {
    const float* X    = (const float*)d_in[0];
    const float* W_ih = (const float*)d_in[1];
    const float* W_hh = (const float*)d_in[2];
    const float* b_ih = (const float*)d_in[3];
    const float* b_hh = (const float*)d_in[4];
    const float* ln_w = (const float*)d_in[5];
    const float* ln_b = (const float*)d_in[6];
    float* out = (float*)d_out;

    prep_kernel<<<(cK * cH + 255) / 256, 256>>>(W_ih, W_hh, b_ih, b_hh);

    cudaFuncSetAttribute(rnn_kernel, cudaFuncAttributeMaxDynamicSharedMemorySize, SMEM_BYTES);
    rnn_kernel<<<GRID, NTHR, SMEM_BYTES>>>(X, ln_w, ln_b, out);
}